// round 1
// baseline (speedup 1.0000x reference)
#include <cuda_runtime.h>
#include <cuda_bf16.h>
#include <cstdint>
#include <cfloat>
#include <math.h>

// Problem constants
#define MB   256      // batch
#define NP   16384    // proxies
#define KD   2048     // feature dim
#define NCL  4096
#define PPOS 4
#define KSEL 54       // BG_KNN + P
#define INV_TEMP 20.0f

// GEMM tiling
#define BM 128
#define BN 128
#define BK 16
#define PAD 20        // floats per smem row (16 + 4) -> conflict-free fragment reads

// Scratch (static device globals; no allocation)
__device__ float g_score[(size_t)MB * NP];
__device__ float g_rowloss[MB];

// ---------------------------------------------------------------------------
// helpers
// ---------------------------------------------------------------------------
__device__ __forceinline__ uint32_t f2tf32(float x) {
    uint32_t r;
    asm("cvt.rna.tf32.f32 %0, %1;" : "=r"(r) : "f"(x));
    return r;
}

__device__ __forceinline__ void mma_tf32(float c[4],
                                         uint32_t a0, uint32_t a1, uint32_t a2, uint32_t a3,
                                         uint32_t b0, uint32_t b1) {
    asm volatile(
        "mma.sync.aligned.m16n8k8.row.col.f32.tf32.tf32.f32 "
        "{%0,%1,%2,%3}, {%4,%5,%6,%7}, {%8,%9}, {%0,%1,%2,%3};\n"
        : "+f"(c[0]), "+f"(c[1]), "+f"(c[2]), "+f"(c[3])
        : "r"(a0), "r"(a1), "r"(a2), "r"(a3), "r"(b0), "r"(b1));
}

__device__ __forceinline__ void cp16(void* smem, const void* g) {
    uint32_t sa = (uint32_t)__cvta_generic_to_shared(smem);
    asm volatile("cp.async.cg.shared.global [%0], [%1], 16;\n" :: "r"(sa), "l"(g));
}
__device__ __forceinline__ void cp_commit() {
    asm volatile("cp.async.commit_group;\n");
}
__device__ __forceinline__ void cp_wait_all() {
    asm volatile("cp.async.wait_group 0;\n");
}

// ---------------------------------------------------------------------------
// Kernel 1: C[256,16384] = A[256,2048] @ B[16384,2048]^T  (TF32 tensor cores)
// Block: 128 threads = 4 warps in 2x2 grid, each warp computes 64x64.
// ---------------------------------------------------------------------------
__global__ __launch_bounds__(128) void gemm_tf32_kernel(const float* __restrict__ A,
                                                        const float* __restrict__ Bg) {
    __shared__ float As[2][BM * PAD];
    __shared__ float Bs[2][BN * PAD];

    const int tid  = threadIdx.x;
    const int lane = tid & 31;
    const int warp = tid >> 5;
    const int wm = (warp >> 1) * 64;   // warp m offset in block tile
    const int wn = (warp & 1) * 64;    // warp n offset in block tile
    const int gM = blockIdx.y * BM;
    const int gN = blockIdx.x * BN;

    float acc[4][8][4];
#pragma unroll
    for (int i = 0; i < 4; ++i)
#pragma unroll
        for (int j = 0; j < 8; ++j)
#pragma unroll
            for (int q = 0; q < 4; ++q) acc[i][j][q] = 0.0f;

    // staging map: thread covers 4 float4 per tile (128 rows x 16 cols)
    const int r0 = tid >> 2;           // 0..31
    const int k4 = (tid & 3) * 4;      // 0,4,8,12

    const int NIT = KD / BK;           // 128

    // prefetch tile 0 into buf 0
    {
        const float* Ag = A + (size_t)gM * KD;
        const float* Bp = Bg + (size_t)gN * KD;
#pragma unroll
        for (int j = 0; j < 4; ++j) {
            int row = r0 + 32 * j;
            cp16(&As[0][row * PAD + k4], Ag + (size_t)row * KD + k4);
            cp16(&Bs[0][row * PAD + k4], Bp + (size_t)row * KD + k4);
        }
        cp_commit();
    }

    int buf = 0;
    for (int it = 0; it < NIT; ++it) {
        cp_wait_all();
        __syncthreads();

        if (it + 1 < NIT) {
            const float* Ag = A + (size_t)gM * KD + (it + 1) * BK;
            const float* Bp = Bg + (size_t)gN * KD + (it + 1) * BK;
            int nb = buf ^ 1;
#pragma unroll
            for (int j = 0; j < 4; ++j) {
                int row = r0 + 32 * j;
                cp16(&As[nb][row * PAD + k4], Ag + (size_t)row * KD + k4);
                cp16(&Bs[nb][row * PAD + k4], Bp + (size_t)row * KD + k4);
            }
            cp_commit();
        }

        // compute on current buf: 2 k-steps of 8
        const int gr = lane >> 2;
        const int kl = lane & 3;
#pragma unroll
        for (int ks = 0; ks < 2; ++ks) {
            const int kb = ks * 8 + kl;
            uint32_t af[4][4];
#pragma unroll
            for (int mt = 0; mt < 4; ++mt) {
                const float* p = &As[buf][(wm + mt * 16 + gr) * PAD + kb];
                af[mt][0] = f2tf32(p[0]);
                af[mt][1] = f2tf32(p[8 * PAD]);
                af[mt][2] = f2tf32(p[4]);
                af[mt][3] = f2tf32(p[8 * PAD + 4]);
            }
            uint32_t bf[8][2];
#pragma unroll
            for (int nt = 0; nt < 8; ++nt) {
                const float* p = &Bs[buf][(wn + nt * 8 + gr) * PAD + kb];
                bf[nt][0] = f2tf32(p[0]);
                bf[nt][1] = f2tf32(p[4]);
            }
#pragma unroll
            for (int mt = 0; mt < 4; ++mt)
#pragma unroll
                for (int nt = 0; nt < 8; ++nt)
                    mma_tf32(acc[mt][nt], af[mt][0], af[mt][1], af[mt][2], af[mt][3],
                             bf[nt][0], bf[nt][1]);
        }
        buf ^= 1;
    }

    // store C (float2 per fragment row pair)
    const int rB = gM + wm + (lane >> 2);
    const int cB = gN + wn + (lane & 3) * 2;
#pragma unroll
    for (int mt = 0; mt < 4; ++mt) {
#pragma unroll
        for (int nt = 0; nt < 8; ++nt) {
            int rr = rB + mt * 16;
            int cc = cB + nt * 8;
            float2 v0 = make_float2(acc[mt][nt][0], acc[mt][nt][1]);
            float2 v1 = make_float2(acc[mt][nt][2], acc[mt][nt][3]);
            *(float2*)&g_score[(size_t)rr * NP + cc] = v0;
            *(float2*)&g_score[(size_t)(rr + 8) * NP + cc] = v1;
        }
    }
}

// ---------------------------------------------------------------------------
// Kernel 2: per-row top-K selection + log-softmax loss
// One block (256 threads) per row. Row cached in dynamic shared memory.
// ---------------------------------------------------------------------------
__global__ void topk_loss_kernel(const int* __restrict__ targets,
                                 const int* __restrict__ apl,
                                 const int* __restrict__ plt) {
    extern __shared__ float sm[];
    float* s   = sm;                 // 16384 scaled scores
    float* lv  = sm + 16384;         // 256 per-thread local max value
    int*   li  = (int*)(sm + 16640); // 256 per-thread local max index
    float* sel = sm + 16896;         // up to 54 selected bg values (descending)

    __shared__ int   posIdx[PPOS];
    __shared__ float posVal[PPOS];
    __shared__ int   nd_s;
    __shared__ int   exIdx;

    const int r = blockIdx.x;
    const int tid = threadIdx.x;
    const float* row = g_score + (size_t)r * NP;

#pragma unroll 8
    for (int j = 0; j < NP / 256; ++j) {
        int i = tid + 256 * j;
        s[i] = row[i] * INV_TEMP;
    }
    __syncthreads();

    if (tid == 0) {
        int t = targets[r];
        int y = apl[t];
        int nd = 0;
        for (int j = 0; j < PPOS; ++j) {
            int p = plt[y * PPOS + j];
            bool dup = false;
            for (int q = 0; q < j; ++q)
                if (plt[y * PPOS + q] == p) dup = true;
            if (!dup) { posIdx[nd] = p; posVal[nd] = s[p]; ++nd; }
        }
        for (int q = 0; q < nd; ++q) s[posIdx[q]] = -FLT_MAX;  // exclude from bg
        nd_s = nd;
    }
    __syncthreads();
    const int nd = nd_s;
    const int nbg = KSEL - nd;

    // per-thread local maxima (indices t, t+256, ..., ascending -> lowest-index tie)
    {
        float bv = -FLT_MAX; int bi = 0x7fffffff;
#pragma unroll 8
        for (int j = 0; j < NP / 256; ++j) {
            int i = tid + 256 * j;
            float v = s[i];
            if (v > bv) { bv = v; bi = i; }
        }
        lv[tid] = bv; li[tid] = bi;
    }
    __syncthreads();

    for (int e = 0; e < nbg; ++e) {
        if (tid < 32) {
            float v = lv[tid]; int idx = li[tid];
#pragma unroll
            for (int o = 32; o < 256; o += 32) {
                float v2 = lv[tid + o]; int i2 = li[tid + o];
                if (v2 > v || (v2 == v && i2 < idx)) { v = v2; idx = i2; }
            }
#pragma unroll
            for (int o = 16; o > 0; o >>= 1) {
                float v2 = __shfl_down_sync(0xffffffffu, v, o);
                int   i2 = __shfl_down_sync(0xffffffffu, idx, o);
                if (v2 > v || (v2 == v && i2 < idx)) { v = v2; idx = i2; }
            }
            if (tid == 0) { sel[e] = v; exIdx = idx; }
        }
        __syncthreads();
        int xi = exIdx;
        if ((xi & 255) == tid) {
            s[xi] = -FLT_MAX;
            float nv = -FLT_MAX; int ni = 0x7fffffff;
#pragma unroll 8
            for (int j = 0; j < NP / 256; ++j) {
                int i = tid + 256 * j;
                float v = s[i];
                if (v > nv) { nv = v; ni = i; }
            }
            lv[tid] = nv; li[tid] = ni;
        }
        __syncthreads();
    }

    if (tid == 0) {
        float m = -FLT_MAX;
        for (int q = 0; q < nd; ++q) m = fmaxf(m, posVal[q]);
        for (int e = 0; e < nbg; ++e) m = fmaxf(m, sel[e]);
        float se = 0.0f;
        for (int q = 0; q < nd; ++q) se += expf(posVal[q] - m);
        for (int e = 0; e < nbg; ++e) se += expf(sel[e] - m);
        float lse = m + logf(se);
        // first P=4 slots: distinct positives, then top background fill
        float f4 = 0.0f;
        for (int q = 0; q < nd; ++q) f4 += posVal[q];
        for (int e = 0; e < PPOS - nd; ++e) f4 += sel[e];
        g_rowloss[r] = lse - 0.25f * f4;
    }
}

// ---------------------------------------------------------------------------
// Kernel 3: mean over 256 row losses -> scalar
// ---------------------------------------------------------------------------
__global__ void reduce_loss_kernel(float* __restrict__ out) {
    __shared__ float sh[256];
    int t = threadIdx.x;
    sh[t] = g_rowloss[t];
    __syncthreads();
#pragma unroll
    for (int o = 128; o > 0; o >>= 1) {
        if (t < o) sh[t] += sh[t + o];
        __syncthreads();
    }
    if (t == 0) out[0] = sh[0] * (1.0f / MB);
}

// ---------------------------------------------------------------------------
// launch
// ---------------------------------------------------------------------------
extern "C" void kernel_launch(void* const* d_in, const int* in_sizes, int n_in,
                              void* d_out, int out_size) {
    const float* features = (const float*)d_in[0];
    const float* em       = (const float*)d_in[1];
    const int*   targets  = (const int*)d_in[2];
    const int*   apl      = (const int*)d_in[3];
    const int*   plt      = (const int*)d_in[4];
    float* out = (float*)d_out;

    const int topk_smem = (16384 + 256 + 256 + 64) * 4;  // 67840 bytes
    cudaFuncSetAttribute(topk_loss_kernel,
                         cudaFuncAttributeMaxDynamicSharedMemorySize, topk_smem);

    dim3 grid(NP / BN, MB / BM);   // (128, 2)
    gemm_tf32_kernel<<<grid, 128>>>(features, em);
    topk_loss_kernel<<<MB, 256, topk_smem>>>(targets, apl, plt);
    reduce_loss_kernel<<<1, 256>>>(out);
}

// round 2
// speedup vs baseline: 1.1270x; 1.1270x over previous
#include <cuda_runtime.h>
#include <cuda_bf16.h>
#include <cstdint>
#include <cfloat>
#include <math.h>

// Problem constants
#define MB   256
#define NP   16384
#define KD   2048
#define PPOS 4
#define KSEL 54
#define INV_TEMP 20.0f

// GEMM tiling
#define BM 128
#define BN 128
#define BK 16
#define PAD 20
#define STAGES 4
#define KSPLIT 2
#define KHALF (KD / KSPLIT)   // 1024

// Scratch
__device__ float g_part[(size_t)KSPLIT * MB * NP];   // split-K partials
__device__ float g_rowloss[MB];

// ---------------------------------------------------------------------------
__device__ __forceinline__ uint32_t f2tf32(float x) {
    uint32_t r;
    asm("cvt.rna.tf32.f32 %0, %1;" : "=r"(r) : "f"(x));
    return r;
}
__device__ __forceinline__ void mma_tf32(float c[4],
                                         uint32_t a0, uint32_t a1, uint32_t a2, uint32_t a3,
                                         uint32_t b0, uint32_t b1) {
    asm volatile(
        "mma.sync.aligned.m16n8k8.row.col.f32.tf32.tf32.f32 "
        "{%0,%1,%2,%3}, {%4,%5,%6,%7}, {%8,%9}, {%0,%1,%2,%3};\n"
        : "+f"(c[0]), "+f"(c[1]), "+f"(c[2]), "+f"(c[3])
        : "r"(a0), "r"(a1), "r"(a2), "r"(a3), "r"(b0), "r"(b1));
}
__device__ __forceinline__ void cp16(void* smem, const void* g) {
    uint32_t sa = (uint32_t)__cvta_generic_to_shared(smem);
    asm volatile("cp.async.cg.shared.global [%0], [%1], 16;\n" :: "r"(sa), "l"(g));
}
__device__ __forceinline__ void cp_commit() { asm volatile("cp.async.commit_group;\n"); }
template <int N> __device__ __forceinline__ void cp_wait() {
    asm volatile("cp.async.wait_group %0;\n" :: "n"(N));
}

// key transform: monotonic float -> uint
__device__ __forceinline__ uint32_t f2key(float v) {
    uint32_t f = __float_as_uint(v);
    return (f & 0x80000000u) ? ~f : (f | 0x80000000u);
}
__device__ __forceinline__ float key2f(uint32_t u) {
    uint32_t f = (u & 0x80000000u) ? (u ^ 0x80000000u) : ~u;
    return __uint_as_float(f);
}

// ---------------------------------------------------------------------------
// Kernel 1: split-K TF32 GEMM. 256 thr = 8 warps (2m x 4n), warp tile 64x32.
// grid (2, 128, 2): m fastest -> both m-blocks of an n-tile share B via L2.
// ---------------------------------------------------------------------------
extern __shared__ float smem_dyn[];

__global__ __launch_bounds__(256, 2) void gemm_tf32_kernel(const float* __restrict__ A,
                                                           const float* __restrict__ B) {
    const int tid  = threadIdx.x;
    const int lane = tid & 31;
    const int warp = tid >> 5;
    const int wm = (warp >> 2) * 64;
    const int wn = (warp & 3) * 32;
    const int gM = blockIdx.x * BM;
    const int gN = blockIdx.y * BN;
    const int kz = blockIdx.z;

    const float* Ag = A + (size_t)gM * KD + kz * KHALF;
    const float* Bg = B + (size_t)gN * KD + kz * KHALF;
    float* out = g_part + (size_t)kz * MB * NP;

    float acc[4][4][4];
#pragma unroll
    for (int i = 0; i < 4; ++i)
#pragma unroll
        for (int j = 0; j < 4; ++j)
#pragma unroll
            for (int q = 0; q < 4; ++q) acc[i][j][q] = 0.0f;

    const int r0 = tid >> 2;           // 0..63
    const int k4 = (tid & 3) * 4;

    float* As = smem_dyn;                       // STAGES * 128*PAD
    float* Bs = smem_dyn + STAGES * BM * PAD;

    const int NIT = KHALF / BK;   // 64

#define PREFETCH(IT, ST)                                                        \
    {                                                                           \
        const float* a_ = Ag + (IT) * BK;                                       \
        const float* b_ = Bg + (IT) * BK;                                       \
        float* as_ = As + (ST) * BM * PAD;                                      \
        float* bs_ = Bs + (ST) * BN * PAD;                                      \
        cp16(&as_[r0 * PAD + k4],        a_ + (size_t)r0 * KD + k4);            \
        cp16(&as_[(r0 + 64) * PAD + k4], a_ + (size_t)(r0 + 64) * KD + k4);     \
        cp16(&bs_[r0 * PAD + k4],        b_ + (size_t)r0 * KD + k4);            \
        cp16(&bs_[(r0 + 64) * PAD + k4], b_ + (size_t)(r0 + 64) * KD + k4);     \
        cp_commit();                                                            \
    }

    PREFETCH(0, 0)
    PREFETCH(1, 1)
    PREFETCH(2, 2)

    const int gr = lane >> 2;
    const int kl = lane & 3;

    for (int it = 0; it < NIT; ++it) {
        const int st = it & 3;
        if (it < NIT - 2)      cp_wait<2>();
        else if (it == NIT - 2) cp_wait<1>();
        else                    cp_wait<0>();
        __syncthreads();

        if (it + 3 < NIT) PREFETCH(it + 3, (it + 3) & 3)

        const float* as = As + st * BM * PAD;
        const float* bs = Bs + st * BN * PAD;
#pragma unroll
        for (int ks = 0; ks < 2; ++ks) {
            const int kb = ks * 8 + kl;
            uint32_t af[4][4];
#pragma unroll
            for (int mt = 0; mt < 4; ++mt) {
                const float* p = &as[(wm + mt * 16 + gr) * PAD + kb];
                af[mt][0] = f2tf32(p[0]);
                af[mt][1] = f2tf32(p[8 * PAD]);
                af[mt][2] = f2tf32(p[4]);
                af[mt][3] = f2tf32(p[8 * PAD + 4]);
            }
            uint32_t bf[4][2];
#pragma unroll
            for (int nt = 0; nt < 4; ++nt) {
                const float* p = &bs[(wn + nt * 8 + gr) * PAD + kb];
                bf[nt][0] = f2tf32(p[0]);
                bf[nt][1] = f2tf32(p[4]);
            }
#pragma unroll
            for (int mt = 0; mt < 4; ++mt)
#pragma unroll
                for (int nt = 0; nt < 4; ++nt)
                    mma_tf32(acc[mt][nt], af[mt][0], af[mt][1], af[mt][2], af[mt][3],
                             bf[nt][0], bf[nt][1]);
        }
    }

    const int rB = gM + wm + (lane >> 2);
    const int cB = gN + wn + (lane & 3) * 2;
#pragma unroll
    for (int mt = 0; mt < 4; ++mt) {
#pragma unroll
        for (int nt = 0; nt < 4; ++nt) {
            int rr = rB + mt * 16;
            int cc = cB + nt * 8;
            *(float2*)&out[(size_t)rr * NP + cc] =
                make_float2(acc[mt][nt][0], acc[mt][nt][1]);
            *(float2*)&out[(size_t)(rr + 8) * NP + cc] =
                make_float2(acc[mt][nt][2], acc[mt][nt][3]);
        }
    }
#undef PREFETCH
}

// ---------------------------------------------------------------------------
// Kernel 2: per-row exact radix-select top-K + log-softmax loss.
// One 256-thread block per row. Keys in dynamic smem (64KB).
// ---------------------------------------------------------------------------
__global__ void topk_loss_kernel(const int* __restrict__ targets,
                                 const int* __restrict__ apl,
                                 const int* __restrict__ plt) {
    extern __shared__ uint32_t skey[];   // 16384 keys
    __shared__ uint32_t hist[256];
    __shared__ uint32_t sfx[256];
    __shared__ float    redf[256];
    __shared__ int      redi[256];
    __shared__ uint32_t s_prefix;
    __shared__ int      s_want;
    __shared__ int      posIdx[PPOS];
    __shared__ float    posVal[PPOS];
    __shared__ int      nd_s;
    __shared__ uint32_t s_maxkey;
    __shared__ float    s_m;
    __shared__ float    s_f4x;
    __shared__ int      s_exIdx;

    const int r = blockIdx.x;
    const int tid = threadIdx.x;
    const float* p0 = g_part + (size_t)r * NP;
    const float* p1 = g_part + (size_t)MB * NP + (size_t)r * NP;

    // 1. load + combine split-K + scale + transform to keys
#pragma unroll 8
    for (int j = 0; j < NP / 256; ++j) {
        int i = tid + 256 * j;
        float v = (p0[i] + p1[i]) * INV_TEMP;
        skey[i] = f2key(v);
    }
    if (tid == 0) { s_maxkey = 0; s_f4x = 0.0f; }
    __syncthreads();

    // 2. positives (dedup), remove from background
    if (tid == 0) {
        int t = targets[r];
        int y = apl[t];
        int nd = 0;
        for (int j = 0; j < PPOS; ++j) {
            int p = plt[y * PPOS + j];
            bool dup = false;
            for (int q = 0; q < j; ++q)
                if (plt[y * PPOS + q] == p) dup = true;
            if (!dup) { posIdx[nd] = p; posVal[nd] = key2f(skey[p]); ++nd; }
        }
        for (int q = 0; q < nd; ++q) skey[posIdx[q]] = 0u;  // exclude
        nd_s = nd;
    }
    __syncthreads();
    const int nd  = nd_s;
    const int nbg = KSEL - nd;

    // 3. radix select: find key threshold T such that exactly nbg keys are
    //    selected (strictly greater ones + `want` copies of T).
    uint32_t prefix = 0;
    int want = nbg;
#pragma unroll
    for (int p = 3; p >= 0; --p) {
        hist[tid] = 0;
        __syncthreads();
        uint32_t lmax = 0;
#pragma unroll 8
        for (int j = 0; j < NP / 256; ++j) {
            uint32_t u = skey[tid + 256 * j];
            if (p == 3) {
                lmax = max(lmax, u);
                atomicAdd(&hist[u >> 24], 1u);
            } else if ((u >> ((p + 1) * 8)) == prefix) {
                atomicAdd(&hist[(u >> (p * 8)) & 0xFFu], 1u);
            }
        }
        if (p == 3) atomicMax(&s_maxkey, lmax);
        __syncthreads();

        // suffix (from-top inclusive) scan of hist into sfx
        uint32_t h = hist[tid];
        sfx[tid] = h;
        __syncthreads();
#pragma unroll
        for (int o = 1; o < 256; o <<= 1) {
            uint32_t v = sfx[tid];
            if (tid + o < 256) v += sfx[tid + o];
            __syncthreads();
            sfx[tid] = v;
            __syncthreads();
        }
        uint32_t excl = sfx[tid] - h;   // count strictly above this bin
        if ((int)excl < want && (int)(excl + h) >= want) {
            s_prefix = (prefix << 8) | (uint32_t)tid;
            s_want = want - (int)excl;
        }
        __syncthreads();
        prefix = s_prefix;
        want = s_want;
        __syncthreads();
    }
    const uint32_t T = prefix;        // exact key of the nbg-th largest
    const int wantEq = want;          // copies of T included

    // 4. m = max over selected set
    if (tid == 0) {
        float m = key2f(s_maxkey);
        for (int q = 0; q < nd; ++q) m = fmaxf(m, posVal[q]);
        s_m = m;
    }
    __syncthreads();
    const float m = s_m;

    // 5. sum of exp over background keys > T
    float se = 0.0f;
#pragma unroll 8
    for (int j = 0; j < NP / 256; ++j) {
        uint32_t u = skey[tid + 256 * j];
        if (u > T) se += expf(key2f(u) - m);
    }
    redf[tid] = se;
    __syncthreads();
#pragma unroll
    for (int o = 128; o > 0; o >>= 1) {
        if (tid < o) redf[tid] += redf[tid + o];
        __syncthreads();
    }

    // 6. rare path: nd < 4 -> need top (4-nd) background values for the
    //    "first P slots" sum (positives occupy nd of the first 4 slots).
    for (int e = 0; e < PPOS - nd; ++e) {
        uint32_t bk = 0; int bi = -1;
#pragma unroll 8
        for (int j = 0; j < NP / 256; ++j) {
            int i = tid + 256 * j;
            uint32_t u = skey[i];
            if (u > bk) { bk = u; bi = i; }
        }
        sfx[tid] = bk; redi[tid] = bi;
        __syncthreads();
#pragma unroll
        for (int o = 128; o > 0; o >>= 1) {
            if (tid < o && sfx[tid + o] > sfx[tid]) {
                sfx[tid] = sfx[tid + o]; redi[tid] = redi[tid + o];
            }
            __syncthreads();
        }
        if (tid == 0) { s_f4x += key2f(sfx[0]); s_exIdx = redi[0]; }
        __syncthreads();
        if ((s_exIdx & 255) == tid) skey[s_exIdx] = 0u;
        __syncthreads();
    }

    // 7. final loss for this row
    if (tid == 0) {
        float seTot = redf[0] + (float)wantEq * expf(key2f(T) - m);
        float f4 = s_f4x;
        for (int q = 0; q < nd; ++q) {
            seTot += expf(posVal[q] - m);
            f4 += posVal[q];
        }
        float lse = m + logf(seTot);
        g_rowloss[r] = lse - 0.25f * f4;
    }
}

// ---------------------------------------------------------------------------
// Kernel 3: mean over 256 row losses
// ---------------------------------------------------------------------------
__global__ void reduce_loss_kernel(float* __restrict__ out) {
    __shared__ float sh[256];
    int t = threadIdx.x;
    sh[t] = g_rowloss[t];
    __syncthreads();
#pragma unroll
    for (int o = 128; o > 0; o >>= 1) {
        if (t < o) sh[t] += sh[t + o];
        __syncthreads();
    }
    if (t == 0) out[0] = sh[0] * (1.0f / MB);
}

// ---------------------------------------------------------------------------
extern "C" void kernel_launch(void* const* d_in, const int* in_sizes, int n_in,
                              void* d_out, int out_size) {
    const float* features = (const float*)d_in[0];
    const float* em       = (const float*)d_in[1];
    const int*   targets  = (const int*)d_in[2];
    const int*   apl      = (const int*)d_in[3];
    const int*   plt      = (const int*)d_in[4];
    float* out = (float*)d_out;

    const int gemm_smem = STAGES * (BM + BN) * PAD * sizeof(float);   // 81920
    cudaFuncSetAttribute(gemm_tf32_kernel,
                         cudaFuncAttributeMaxDynamicSharedMemorySize, gemm_smem);
    const int topk_smem = NP * sizeof(uint32_t);                      // 65536
    cudaFuncSetAttribute(topk_loss_kernel,
                         cudaFuncAttributeMaxDynamicSharedMemorySize, topk_smem);

    dim3 grid(MB / BM, NP / BN, KSPLIT);   // (2, 128, 2)
    gemm_tf32_kernel<<<grid, 256, gemm_smem>>>(features, em);
    topk_loss_kernel<<<MB, 256, topk_smem>>>(targets, apl, plt);
    reduce_loss_kernel<<<1, 256>>>(out);
}

// round 3
// speedup vs baseline: 2.0529x; 1.8215x over previous
#include <cuda_runtime.h>
#include <cuda_bf16.h>
#include <cstdint>
#include <cfloat>
#include <math.h>

// Problem constants
#define MB   256
#define NP   16384
#define KD   2048
#define PPOS 4
#define KSEL 54
#define INV_TEMP 20.0f

// GEMM tiling
#define BM 256
#define BN 128
#define BK 32
#define NTHR 512
#define NIT (KD / BK)          // 64
#define LDS_ROW 40             // bf16 per smem row (32 + 8 pad) -> conflict-free

// Scratch
__device__ __nv_bfloat16 g_Abf[(size_t)MB * KD];
__device__ float g_score[(size_t)MB * NP];
__device__ float g_rowloss[MB];

// ---------------------------------------------------------------------------
__device__ __forceinline__ void mma_bf16(float c[4],
                                         uint32_t a0, uint32_t a1, uint32_t a2, uint32_t a3,
                                         uint32_t b0, uint32_t b1) {
    asm volatile(
        "mma.sync.aligned.m16n8k16.row.col.f32.bf16.bf16.f32 "
        "{%0,%1,%2,%3}, {%4,%5,%6,%7}, {%8,%9}, {%0,%1,%2,%3};\n"
        : "+f"(c[0]), "+f"(c[1]), "+f"(c[2]), "+f"(c[3])
        : "r"(a0), "r"(a1), "r"(a2), "r"(a3), "r"(b0), "r"(b1));
}
__device__ __forceinline__ void cp16(void* smem, const void* g) {
    uint32_t sa = (uint32_t)__cvta_generic_to_shared(smem);
    asm volatile("cp.async.cg.shared.global [%0], [%1], 16;\n" :: "r"(sa), "l"(g));
}
__device__ __forceinline__ void cp_commit() { asm volatile("cp.async.commit_group;\n"); }
__device__ __forceinline__ void cp_wait0()  { asm volatile("cp.async.wait_group 0;\n"); }

__device__ __forceinline__ uint32_t f2key(float v) {
    uint32_t f = __float_as_uint(v);
    return (f & 0x80000000u) ? ~f : (f | 0x80000000u);
}
__device__ __forceinline__ float key2f(uint32_t u) {
    uint32_t f = (u & 0x80000000u) ? (u ^ 0x80000000u) : ~u;
    return __uint_as_float(f);
}
__device__ __forceinline__ uint32_t pack_bf16x2(float x, float y) {
    __nv_bfloat162 h = __floats2bfloat162_rn(x, y);
    return *(uint32_t*)&h;
}

// ---------------------------------------------------------------------------
// Kernel 0: convert A (256x2048 fp32) to bf16 once.
// ---------------------------------------------------------------------------
__global__ void convertA_kernel(const float* __restrict__ A) {
    int i = blockIdx.x * blockDim.x + threadIdx.x;   // 131072 float4 total
    float4 v = ((const float4*)A)[i];
    uint2 o = make_uint2(pack_bf16x2(v.x, v.y), pack_bf16x2(v.z, v.w));
    ((uint2*)g_Abf)[i] = o;
}

// ---------------------------------------------------------------------------
// Kernel 1: C[256,16384] = A @ B^T, bf16 tensor cores.
// One block covers all of M (BM=256); grid = 128 n-tiles (single wave).
// A staged via cp.async (bf16 global), B converted fp32->bf16 inline.
// 512 threads = 16 warps (4m x 4n), warp tile 64x32, BK=32 (2 k16 steps).
// ---------------------------------------------------------------------------
extern __shared__ __nv_bfloat16 smem_bf[];

__global__ __launch_bounds__(NTHR, 1) void gemm_bf16_kernel(const float* __restrict__ B) {
    const int tid  = threadIdx.x;
    const int lane = tid & 31;
    const int warp = tid >> 5;
    const int wm = (warp >> 2) * 64;
    const int wn = (warp & 3) * 32;
    const int gN = blockIdx.x * BN;
    const int gr = lane >> 2;
    const int kl = lane & 3;

    __nv_bfloat16* As = smem_bf;                       // 2 stages * 256*40
    __nv_bfloat16* Bs = smem_bf + 2 * BM * LDS_ROW;    // 2 stages * 128*40

    float acc[4][4][4];
#pragma unroll
    for (int i = 0; i < 4; ++i)
#pragma unroll
        for (int j = 0; j < 4; ++j)
#pragma unroll
            for (int q = 0; q < 4; ++q) acc[i][j][q] = 0.0f;

    // A staging: 1024 16B-chunks per stage; thread does chunks {tid, tid+512}
    const int arow0 = tid >> 2;            // chunk tid   -> rows 0..127
    const int arow1 = (tid + NTHR) >> 2;   // chunk tid+512 -> rows 128..255
    const int acol  = (tid & 3) * 8;       // bf16 col
    // B staging: 1024 float4-chunks per stage; thread does {tid, tid+512}
    const int brow0 = tid >> 3;            // rows 0..63
    const int brow1 = (tid + NTHR) >> 3;   // rows 64..127
    const int bcol  = (tid & 7) * 4;       // fp32 col

    const float* Bp = B + (size_t)gN * KD;

    float4 breg0, breg1;

    // prologue: LDG B tile 0, cp.async A tile 0
    breg0 = *(const float4*)(Bp + (size_t)brow0 * KD + bcol);
    breg1 = *(const float4*)(Bp + (size_t)brow1 * KD + bcol);
    cp16(&As[arow0 * LDS_ROW + acol], g_Abf + (size_t)arow0 * KD + acol);
    cp16(&As[arow1 * LDS_ROW + acol], g_Abf + (size_t)arow1 * KD + acol);
    cp_commit();

    for (int it = 0; it < NIT; ++it) {
        const int st = it & 1;
        __nv_bfloat16* as_ = As + st * BM * LDS_ROW;
        __nv_bfloat16* bs_ = Bs + st * BN * LDS_ROW;

        cp_wait0();
        __syncthreads();   // A_it visible; stage st free

        // store B_it (convert fp32 -> bf16)
        *(uint2*)&bs_[brow0 * LDS_ROW + bcol] =
            make_uint2(pack_bf16x2(breg0.x, breg0.y), pack_bf16x2(breg0.z, breg0.w));
        *(uint2*)&bs_[brow1 * LDS_ROW + bcol] =
            make_uint2(pack_bf16x2(breg1.x, breg1.y), pack_bf16x2(breg1.z, breg1.w));

        // prefetch next tile
        if (it + 1 < NIT) {
            const int ko = (it + 1) * BK;
            breg0 = *(const float4*)(Bp + (size_t)brow0 * KD + ko + bcol);
            breg1 = *(const float4*)(Bp + (size_t)brow1 * KD + ko + bcol);
            __nv_bfloat16* an_ = As + (st ^ 1) * BM * LDS_ROW;
            cp16(&an_[arow0 * LDS_ROW + acol], g_Abf + (size_t)arow0 * KD + ko + acol);
            cp16(&an_[arow1 * LDS_ROW + acol], g_Abf + (size_t)arow1 * KD + ko + acol);
            cp_commit();
        }
        __syncthreads();   // B_it visible

        const uint32_t* as32 = (const uint32_t*)as_;
        const uint32_t* bs32 = (const uint32_t*)bs_;
#pragma unroll
        for (int s = 0; s < 2; ++s) {
            const int co = s * 8 + kl;    // b32 col
            uint32_t a[4][4];
#pragma unroll
            for (int mt = 0; mt < 4; ++mt) {
                const int r0 = (wm + mt * 16 + gr) * (LDS_ROW / 2);
                a[mt][0] = as32[r0 + co];
                a[mt][1] = as32[r0 + 8 * (LDS_ROW / 2) + co];
                a[mt][2] = as32[r0 + co + 4];
                a[mt][3] = as32[r0 + 8 * (LDS_ROW / 2) + co + 4];
            }
            uint32_t b[4][2];
#pragma unroll
            for (int nt = 0; nt < 4; ++nt) {
                const int rb = (wn + nt * 8 + gr) * (LDS_ROW / 2);
                b[nt][0] = bs32[rb + co];
                b[nt][1] = bs32[rb + co + 4];
            }
#pragma unroll
            for (int mt = 0; mt < 4; ++mt)
#pragma unroll
                for (int nt = 0; nt < 4; ++nt)
                    mma_bf16(acc[mt][nt], a[mt][0], a[mt][1], a[mt][2], a[mt][3],
                             b[nt][0], b[nt][1]);
        }
    }

    // epilogue
    const int rB = wm + gr;
    const int cB = gN + wn + (lane & 3) * 2;
#pragma unroll
    for (int mt = 0; mt < 4; ++mt) {
#pragma unroll
        for (int nt = 0; nt < 4; ++nt) {
            int rr = rB + mt * 16;
            int cc = cB + nt * 8;
            *(float2*)&g_score[(size_t)rr * NP + cc] =
                make_float2(acc[mt][nt][0], acc[mt][nt][1]);
            *(float2*)&g_score[(size_t)(rr + 8) * NP + cc] =
                make_float2(acc[mt][nt][2], acc[mt][nt][3]);
        }
    }
}

// ---------------------------------------------------------------------------
// Kernel 2: per-row exact radix-select top-K + log-softmax loss.
// ---------------------------------------------------------------------------
__global__ void topk_loss_kernel(const int* __restrict__ targets,
                                 const int* __restrict__ apl,
                                 const int* __restrict__ plt) {
    extern __shared__ uint32_t skey[];   // 16384 keys
    __shared__ uint32_t hist[256];
    __shared__ uint32_t sfx[256];
    __shared__ float    redf[256];
    __shared__ int      redi[256];
    __shared__ uint32_t s_prefix;
    __shared__ int      s_want;
    __shared__ int      posIdx[PPOS];
    __shared__ float    posVal[PPOS];
    __shared__ int      nd_s;
    __shared__ uint32_t s_maxkey;
    __shared__ float    s_m;
    __shared__ float    s_f4x;
    __shared__ int      s_exIdx;

    const int r = blockIdx.x;
    const int tid = threadIdx.x;
    const float4* row4 = (const float4*)(g_score + (size_t)r * NP);

#pragma unroll 4
    for (int j = 0; j < NP / 4 / 256; ++j) {    // 16 float4 per thread
        int i = tid + 256 * j;
        float4 v = row4[i];
        skey[i * 4 + 0] = f2key(v.x * INV_TEMP);
        skey[i * 4 + 1] = f2key(v.y * INV_TEMP);
        skey[i * 4 + 2] = f2key(v.z * INV_TEMP);
        skey[i * 4 + 3] = f2key(v.w * INV_TEMP);
    }
    if (tid == 0) { s_maxkey = 0; s_f4x = 0.0f; }
    __syncthreads();

    if (tid == 0) {
        int t = targets[r];
        int y = apl[t];
        int nd = 0;
        for (int j = 0; j < PPOS; ++j) {
            int p = plt[y * PPOS + j];
            bool dup = false;
            for (int q = 0; q < j; ++q)
                if (plt[y * PPOS + q] == p) dup = true;
            if (!dup) { posIdx[nd] = p; posVal[nd] = key2f(skey[p]); ++nd; }
        }
        for (int q = 0; q < nd; ++q) skey[posIdx[q]] = 0u;
        nd_s = nd;
    }
    __syncthreads();
    const int nd  = nd_s;
    const int nbg = KSEL - nd;

    // radix select: threshold key T with `want` copies included
    uint32_t prefix = 0;
    int want = nbg;
#pragma unroll
    for (int p = 3; p >= 0; --p) {
        hist[tid] = 0;
        __syncthreads();
        uint32_t lmax = 0;
#pragma unroll 8
        for (int j = 0; j < NP / 256; ++j) {
            uint32_t u = skey[tid + 256 * j];
            if (p == 3) {
                lmax = max(lmax, u);
                atomicAdd(&hist[u >> 24], 1u);
            } else if ((u >> ((p + 1) * 8)) == prefix) {
                atomicAdd(&hist[(u >> (p * 8)) & 0xFFu], 1u);
            }
        }
        if (p == 3) atomicMax(&s_maxkey, lmax);
        __syncthreads();

        uint32_t h = hist[tid];
        sfx[tid] = h;
        __syncthreads();
#pragma unroll
        for (int o = 1; o < 256; o <<= 1) {
            uint32_t v = sfx[tid];
            if (tid + o < 256) v += sfx[tid + o];
            __syncthreads();
            sfx[tid] = v;
            __syncthreads();
        }
        uint32_t excl = sfx[tid] - h;
        if ((int)excl < want && (int)(excl + h) >= want) {
            s_prefix = (prefix << 8) | (uint32_t)tid;
            s_want = want - (int)excl;
        }
        __syncthreads();
        prefix = s_prefix;
        want = s_want;
        __syncthreads();
    }
    const uint32_t T = prefix;
    const int wantEq = want;

    if (tid == 0) {
        float m = key2f(s_maxkey);
        for (int q = 0; q < nd; ++q) m = fmaxf(m, posVal[q]);
        s_m = m;
    }
    __syncthreads();
    const float m = s_m;

    float se = 0.0f;
#pragma unroll 8
    for (int j = 0; j < NP / 256; ++j) {
        uint32_t u = skey[tid + 256 * j];
        if (u > T) se += expf(key2f(u) - m);
    }
    redf[tid] = se;
    __syncthreads();
#pragma unroll
    for (int o = 128; o > 0; o >>= 1) {
        if (tid < o) redf[tid] += redf[tid + o];
        __syncthreads();
    }

    // rare: nd < 4 -> top (4-nd) background values complete the first-P sum
    for (int e = 0; e < PPOS - nd; ++e) {
        uint32_t bk = 0; int bi = -1;
#pragma unroll 8
        for (int j = 0; j < NP / 256; ++j) {
            int i = tid + 256 * j;
            uint32_t u = skey[i];
            if (u > bk) { bk = u; bi = i; }
        }
        sfx[tid] = bk; redi[tid] = bi;
        __syncthreads();
#pragma unroll
        for (int o = 128; o > 0; o >>= 1) {
            if (tid < o && sfx[tid + o] > sfx[tid]) {
                sfx[tid] = sfx[tid + o]; redi[tid] = redi[tid + o];
            }
            __syncthreads();
        }
        if (tid == 0) { s_f4x += key2f(sfx[0]); s_exIdx = redi[0]; }
        __syncthreads();
        if ((s_exIdx & 255) == tid) skey[s_exIdx] = 0u;
        __syncthreads();
    }

    if (tid == 0) {
        float seTot = redf[0] + (float)wantEq * expf(key2f(T) - m);
        float f4 = s_f4x;
        for (int q = 0; q < nd; ++q) {
            seTot += expf(posVal[q] - m);
            f4 += posVal[q];
        }
        float lse = m + logf(seTot);
        g_rowloss[r] = lse - 0.25f * f4;
    }
}

// ---------------------------------------------------------------------------
__global__ void reduce_loss_kernel(float* __restrict__ out) {
    __shared__ float sh[256];
    int t = threadIdx.x;
    sh[t] = g_rowloss[t];
    __syncthreads();
#pragma unroll
    for (int o = 128; o > 0; o >>= 1) {
        if (t < o) sh[t] += sh[t + o];
        __syncthreads();
    }
    if (t == 0) out[0] = sh[0] * (1.0f / MB);
}

// ---------------------------------------------------------------------------
extern "C" void kernel_launch(void* const* d_in, const int* in_sizes, int n_in,
                              void* d_out, int out_size) {
    const float* features = (const float*)d_in[0];
    const float* em       = (const float*)d_in[1];
    const int*   targets  = (const int*)d_in[2];
    const int*   apl      = (const int*)d_in[3];
    const int*   plt      = (const int*)d_in[4];
    float* out = (float*)d_out;

    const int gemm_smem = 2 * (BM + BN) * LDS_ROW * sizeof(__nv_bfloat16);  // 61440
    cudaFuncSetAttribute(gemm_bf16_kernel,
                         cudaFuncAttributeMaxDynamicSharedMemorySize, gemm_smem);
    const int topk_smem = NP * sizeof(uint32_t);                            // 65536
    cudaFuncSetAttribute(topk_loss_kernel,
                         cudaFuncAttributeMaxDynamicSharedMemorySize, topk_smem);

    convertA_kernel<<<(MB * KD / 4) / 128, 128>>>(features);
    gemm_bf16_kernel<<<NP / BN, NTHR, gemm_smem>>>(em);
    topk_loss_kernel<<<MB, 256, topk_smem>>>(targets, apl, plt);
    reduce_loss_kernel<<<1, 256>>>(out);
}

// round 5
// speedup vs baseline: 2.6643x; 1.2979x over previous
#include <cuda_runtime.h>
#include <cuda_bf16.h>
#include <cstdint>
#include <cfloat>
#include <math.h>

// Problem constants
#define MB   256
#define NP   16384
#define KD   2048
#define PPOS 4
#define KSEL 54
#define INV_TEMP 20.0f

// GEMM tiling: BM=256 (all of M), BN=128, BK=64. 8 warps (4m x 2n), warp 64x64.
#define BN 128
#define BK 64
#define NTHR 256
#define GNIT (KD / BK)          // 32
#define A_STAGE 32768           // 256 rows * 128 B
#define B_STAGE 16384           // 128 rows * 128 B

// Scratch
__device__ __nv_bfloat16 g_Abf[(size_t)MB * KD];
__device__ float g_score[(size_t)MB * NP];

// ---------------------------------------------------------------------------
__device__ __forceinline__ uint32_t smem_u32(const void* p) {
    uint32_t a;
    asm("{ .reg .u64 t; cvta.to.shared.u64 t, %1; cvt.u32.u64 %0, t; }"
        : "=r"(a) : "l"(p));
    return a;
}
__device__ __forceinline__ void cp16(uint32_t sa, const void* g) {
    asm volatile("cp.async.cg.shared.global [%0], [%1], 16;\n" :: "r"(sa), "l"(g));
}
__device__ __forceinline__ void cp_commit() { asm volatile("cp.async.commit_group;\n"); }
__device__ __forceinline__ void cp_wait0()  { asm volatile("cp.async.wait_group 0;\n"); }

__device__ __forceinline__ void mma_bf16(float c[4],
                                         uint32_t a0, uint32_t a1, uint32_t a2, uint32_t a3,
                                         uint32_t b0, uint32_t b1) {
    asm volatile(
        "mma.sync.aligned.m16n8k16.row.col.f32.bf16.bf16.f32 "
        "{%0,%1,%2,%3}, {%4,%5,%6,%7}, {%8,%9}, {%0,%1,%2,%3};\n"
        : "+f"(c[0]), "+f"(c[1]), "+f"(c[2]), "+f"(c[3])
        : "r"(a0), "r"(a1), "r"(a2), "r"(a3), "r"(b0), "r"(b1));
}
__device__ __forceinline__ void ldsm4(uint32_t& r0, uint32_t& r1, uint32_t& r2,
                                      uint32_t& r3, uint32_t addr) {
    asm volatile("ldmatrix.sync.aligned.m8n8.x4.shared.b16 {%0,%1,%2,%3}, [%4];"
                 : "=r"(r0), "=r"(r1), "=r"(r2), "=r"(r3) : "r"(addr));
}
__device__ __forceinline__ uint32_t pk(float x, float y) {
    __nv_bfloat162 h = __floats2bfloat162_rn(x, y);
    return *(uint32_t*)&h;
}
__device__ __forceinline__ uint32_t f2key(float v) {
    uint32_t f = __float_as_uint(v);
    return (f & 0x80000000u) ? ~f : (f | 0x80000000u);
}
__device__ __forceinline__ float key2f(uint32_t u) {
    uint32_t f = (u & 0x80000000u) ? (u ^ 0x80000000u) : ~u;
    return __uint_as_float(f);
}
#define SWZ(o) ((o) ^ ((((uint32_t)(o)) >> 3) & 0x70))

// ---------------------------------------------------------------------------
// Kernel 0: convert A to bf16 once; thread 0 zeroes the output scalar.
// ---------------------------------------------------------------------------
__global__ void convertA_kernel(const float* __restrict__ A, float* __restrict__ out) {
    int i = blockIdx.x * blockDim.x + threadIdx.x;
    float4 v = ((const float4*)A)[i];
    ((uint2*)g_Abf)[i] = make_uint2(pk(v.x, v.y), pk(v.z, v.w));
    if (i == 0) out[0] = 0.0f;
}

// ---------------------------------------------------------------------------
// Kernel 1: C[256,16384] = A @ B^T, bf16 mma.sync + ldmatrix.
// Grid 128 (n-tiles), 256 threads = 8 warps (4m x 2n), warp tile 64x64.
// ---------------------------------------------------------------------------
extern __shared__ char smem_g[];

__global__ __launch_bounds__(NTHR, 1) void gemm_bf16_kernel(const float* __restrict__ B) {
    const uint32_t sbase = smem_u32(smem_g);
    const uint32_t Asu = sbase;                     // 2 stages A
    const uint32_t Bsu = sbase + 2 * A_STAGE;       // 2 stages B
    char* Bsg = smem_g + 2 * A_STAGE;

    const int tid  = threadIdx.x;
    const int lane = tid & 31;
    const int warp = tid >> 5;
    const int wm = (warp >> 1) * 64;
    const int wn = (warp & 1) * 64;
    const int gN = blockIdx.x * BN;

    // ldmatrix lane roles
    const int rowin = lane & 7;
    const int ph    = lane >> 3;                    // 0..3
    const int mArow = (ph & 1) * 8 + rowin;         // A: row-in-16 block
    const int kAoff = (ph >> 1) * 16;               // A: 16B k-phase
    const int nBrow = (ph >> 1) * 8 + rowin;        // B: row-in-16 block
    const int kBoff = (ph & 1) * 16;                // B: 16B k-phase

    float acc[4][8][4];
#pragma unroll
    for (int i = 0; i < 4; ++i)
#pragma unroll
        for (int j = 0; j < 8; ++j)
#pragma unroll
            for (int q = 0; q < 4; ++q) acc[i][j][q] = 0.0f;

    const float* Bg = B + (size_t)gN * KD;

    // B register prefetch: 4 output 16B-segments per thread (2 float4 each)
    float4 br0[4], br1[4];
#pragma unroll
    for (int j = 0; j < 4; ++j) {
        int id = tid + 256 * j, r = id >> 3, sg = id & 7;
        const float* s = Bg + (size_t)r * KD + sg * 8;
        br0[j] = *(const float4*)s;
        br1[j] = *(const float4*)(s + 4);
    }
    // A tile 0 via cp.async (8 chunks/thread)
#pragma unroll
    for (int j = 0; j < 8; ++j) {
        int id = tid + 256 * j, r = id >> 3, c = id & 7;
        cp16(Asu + SWZ(r * 128 + c * 16), g_Abf + (size_t)r * KD + c * 8);
    }
    cp_commit();

    for (int it = 0; it < GNIT; ++it) {
        const int st = it & 1;
        cp_wait0();
        __syncthreads();

        // STS B_it (convert prefetched fp32 -> bf16, swizzled)
#pragma unroll
        for (int j = 0; j < 4; ++j) {
            int id = tid + 256 * j, r = id >> 3, sg = id & 7;
            uint4 v = make_uint4(pk(br0[j].x, br0[j].y), pk(br0[j].z, br0[j].w),
                                 pk(br1[j].x, br1[j].y), pk(br1[j].z, br1[j].w));
            *(uint4*)(Bsg + st * B_STAGE + SWZ(r * 128 + sg * 16)) = v;
        }

        if (it + 1 < GNIT) {
            const int ko = (it + 1) * BK;
            // prefetch next B
#pragma unroll
            for (int j = 0; j < 4; ++j) {
                int id = tid + 256 * j, r = id >> 3, sg = id & 7;
                const float* s = Bg + (size_t)r * KD + ko + sg * 8;
                br0[j] = *(const float4*)s;
                br1[j] = *(const float4*)(s + 4);
            }
            // cp.async next A
            const uint32_t an = Asu + (st ^ 1) * A_STAGE;
#pragma unroll
            for (int j = 0; j < 8; ++j) {
                int id = tid + 256 * j, r = id >> 3, c = id & 7;
                cp16(an + SWZ(r * 128 + c * 16), g_Abf + (size_t)r * KD + ko + c * 8);
            }
            cp_commit();
        }
        __syncthreads();

        const uint32_t ab = Asu + st * A_STAGE;
        const uint32_t bb = Bsu + st * B_STAGE;
#pragma unroll
        for (int s = 0; s < 4; ++s) {
            const int kb = s * 32;
            uint32_t a[4][4];
#pragma unroll
            for (int mt = 0; mt < 4; ++mt) {
                int m = wm + mt * 16 + mArow;
                ldsm4(a[mt][0], a[mt][1], a[mt][2], a[mt][3],
                      ab + SWZ(m * 128 + kb + kAoff));
            }
            uint32_t b[8][2];
#pragma unroll
            for (int np = 0; np < 4; ++np) {
                int n = wn + np * 16 + nBrow;
                ldsm4(b[np * 2][0], b[np * 2][1], b[np * 2 + 1][0], b[np * 2 + 1][1],
                      bb + SWZ(n * 128 + kb + kBoff));
            }
#pragma unroll
            for (int mt = 0; mt < 4; ++mt)
#pragma unroll
                for (int nt = 0; nt < 8; ++nt)
                    mma_bf16(acc[mt][nt], a[mt][0], a[mt][1], a[mt][2], a[mt][3],
                             b[nt][0], b[nt][1]);
        }
    }

    // epilogue
    const int gr = lane >> 2;
    const int cB = gN + wn + (lane & 3) * 2;
#pragma unroll
    for (int mt = 0; mt < 4; ++mt) {
#pragma unroll
        for (int nt = 0; nt < 8; ++nt) {
            int rr = wm + mt * 16 + gr;
            int cc = cB + nt * 8;
            *(float2*)&g_score[(size_t)rr * NP + cc] =
                make_float2(acc[mt][nt][0], acc[mt][nt][1]);
            *(float2*)&g_score[(size_t)(rr + 8) * NP + cc] =
                make_float2(acc[mt][nt][2], acc[mt][nt][3]);
        }
    }
}

// ---------------------------------------------------------------------------
// Kernel 2: per-row exact radix-select top-K + log-softmax loss + fused mean.
// ---------------------------------------------------------------------------
__global__ void topk_loss_kernel(const int* __restrict__ targets,
                                 const int* __restrict__ apl,
                                 const int* __restrict__ plt,
                                 float* __restrict__ out) {
    extern __shared__ uint32_t skey[];   // 16384 keys
    __shared__ uint32_t hist[256];
    __shared__ uint32_t sfx[256];
    __shared__ float    redf[256];
    __shared__ int      redi[256];
    __shared__ uint32_t s_prefix;
    __shared__ int      s_want;
    __shared__ int      posIdx[PPOS];
    __shared__ float    posVal[PPOS];
    __shared__ int      nd_s;
    __shared__ uint32_t s_maxkey;
    __shared__ float    s_m;
    __shared__ float    s_f4x;
    __shared__ int      s_exIdx;

    const int r = blockIdx.x;
    const int tid = threadIdx.x;
    const float4* row4 = (const float4*)(g_score + (size_t)r * NP);

#pragma unroll 4
    for (int j = 0; j < NP / 4 / 256; ++j) {
        int i = tid + 256 * j;
        float4 v = row4[i];
        skey[i * 4 + 0] = f2key(v.x * INV_TEMP);
        skey[i * 4 + 1] = f2key(v.y * INV_TEMP);
        skey[i * 4 + 2] = f2key(v.z * INV_TEMP);
        skey[i * 4 + 3] = f2key(v.w * INV_TEMP);
    }
    if (tid == 0) { s_maxkey = 0; s_f4x = 0.0f; }
    __syncthreads();

    if (tid == 0) {
        int t = targets[r];
        int y = apl[t];
        int nd = 0;
        for (int j = 0; j < PPOS; ++j) {
            int p = plt[y * PPOS + j];
            bool dup = false;
            for (int q = 0; q < j; ++q)
                if (plt[y * PPOS + q] == p) dup = true;
            if (!dup) { posIdx[nd] = p; posVal[nd] = key2f(skey[p]); ++nd; }
        }
        for (int q = 0; q < nd; ++q) skey[posIdx[q]] = 0u;
        nd_s = nd;
    }
    __syncthreads();
    const int nd  = nd_s;
    const int nbg = KSEL - nd;

    uint32_t prefix = 0;
    int want = nbg;
#pragma unroll
    for (int p = 3; p >= 0; --p) {
        hist[tid] = 0;
        __syncthreads();
        uint32_t lmax = 0;
#pragma unroll 8
        for (int j = 0; j < NP / 256; ++j) {
            uint32_t u = skey[tid + 256 * j];
            if (p == 3) {
                lmax = max(lmax, u);
                atomicAdd(&hist[u >> 24], 1u);
            } else if ((u >> ((p + 1) * 8)) == prefix) {
                atomicAdd(&hist[(u >> (p * 8)) & 0xFFu], 1u);
            }
        }
        if (p == 3) atomicMax(&s_maxkey, lmax);
        __syncthreads();

        uint32_t h = hist[tid];
        sfx[tid] = h;
        __syncthreads();
#pragma unroll
        for (int o = 1; o < 256; o <<= 1) {
            uint32_t v = sfx[tid];
            if (tid + o < 256) v += sfx[tid + o];
            __syncthreads();
            sfx[tid] = v;
            __syncthreads();
        }
        uint32_t excl = sfx[tid] - h;
        if ((int)excl < want && (int)(excl + h) >= want) {
            s_prefix = (prefix << 8) | (uint32_t)tid;
            s_want = want - (int)excl;
        }
        __syncthreads();
        prefix = s_prefix;
        want = s_want;
        __syncthreads();
    }
    const uint32_t T = prefix;
    const int wantEq = want;

    if (tid == 0) {
        float m = key2f(s_maxkey);
        for (int q = 0; q < nd; ++q) m = fmaxf(m, posVal[q]);
        s_m = m;
    }
    __syncthreads();
    const float m = s_m;

    float se = 0.0f;
#pragma unroll 8
    for (int j = 0; j < NP / 256; ++j) {
        uint32_t u = skey[tid + 256 * j];
        if (u > T) se += expf(key2f(u) - m);
    }
    redf[tid] = se;
    __syncthreads();
#pragma unroll
    for (int o = 128; o > 0; o >>= 1) {
        if (tid < o) redf[tid] += redf[tid + o];
        __syncthreads();
    }

    // rare: nd < 4 -> top (4-nd) background values complete the first-P sum
    for (int e = 0; e < PPOS - nd; ++e) {
        uint32_t bk = 0; int bi = -1;
#pragma unroll 8
        for (int j = 0; j < NP / 256; ++j) {
            int i = tid + 256 * j;
            uint32_t u = skey[i];
            if (u > bk) { bk = u; bi = i; }
        }
        sfx[tid] = bk; redi[tid] = bi;
        __syncthreads();
#pragma unroll
        for (int o = 128; o > 0; o >>= 1) {
            if (tid < o && sfx[tid + o] > sfx[tid]) {
                sfx[tid] = sfx[tid + o]; redi[tid] = redi[tid + o];
            }
            __syncthreads();
        }
        if (tid == 0) { s_f4x += key2f(sfx[0]); s_exIdx = redi[0]; }
        __syncthreads();
        if ((s_exIdx & 255) == tid) skey[s_exIdx] = 0u;
        __syncthreads();
    }

    if (tid == 0) {
        float seTot = redf[0] + (float)wantEq * expf(key2f(T) - m);
        float f4 = s_f4x;
        for (int q = 0; q < nd; ++q) {
            seTot += expf(posVal[q] - m);
            f4 += posVal[q];
        }
        float lse = m + logf(seTot);
        atomicAdd(out, (lse - 0.25f * f4) * (1.0f / MB));
    }
}

// ---------------------------------------------------------------------------
extern "C" void kernel_launch(void* const* d_in, const int* in_sizes, int n_in,
                              void* d_out, int out_size) {
    const float* features = (const float*)d_in[0];
    const float* em       = (const float*)d_in[1];
    const int*   targets  = (const int*)d_in[2];
    const int*   apl      = (const int*)d_in[3];
    const int*   plt      = (const int*)d_in[4];
    float* out = (float*)d_out;

    const int gemm_smem = 2 * (A_STAGE + B_STAGE);   // 98304
    cudaFuncSetAttribute(gemm_bf16_kernel,
                         cudaFuncAttributeMaxDynamicSharedMemorySize, gemm_smem);
    const int topk_smem = NP * sizeof(uint32_t);     // 65536
    cudaFuncSetAttribute(topk_loss_kernel,
                         cudaFuncAttributeMaxDynamicSharedMemorySize, topk_smem);

    convertA_kernel<<<(MB * KD / 4) / 128, 128>>>(features, out);
    gemm_bf16_kernel<<<NP / BN, NTHR, gemm_smem>>>(em);
    topk_loss_kernel<<<MB, 256, topk_smem>>>(targets, apl, plt, out);
}